// round 10
// baseline (speedup 1.0000x reference)
#include <cuda_runtime.h>

typedef unsigned long long u64;
typedef unsigned int u32;

#define CAP 2097152
#define EPSBN 1e-5f
#define SGRID 1184

__device__ float4 g_h2[4 * CAP];                    // h2 plane-major: [plane p][row]
__device__ float g_stats[5][32];                    // [stage][sum 0..15 | sumsq 0..15]
__device__ __align__(16) float g_ctab[8 * 64];      // emb@wc_tail^T + bc

// ---------------- packed f32x2 helpers ----------------
__device__ __forceinline__ u64 pack2(float x, float y) {
  u64 d;
  asm("mov.b64 %0, {%1, %2};" : "=l"(d) : "r"(__float_as_uint(x)), "r"(__float_as_uint(y)));
  return d;
}
__device__ __forceinline__ void unpack2(u64 a, float& x, float& y) {
  u32 lo, hi;
  asm("mov.b64 {%0, %1}, %2;" : "=r"(lo), "=r"(hi) : "l"(a));
  x = __uint_as_float(lo); y = __uint_as_float(hi);
}
__device__ __forceinline__ u64 fma2(u64 a, u64 b, u64 c) {
  u64 d;
  asm("fma.rn.f32x2 %0, %1, %2, %3;" : "=l"(d) : "l"(a), "l"(b), "l"(c));
  return d;
}
__device__ __forceinline__ u64 add2(u64 a, u64 b) {
  u64 d;
  asm("add.rn.f32x2 %0, %1, %2;" : "=l"(d) : "l"(a), "l"(b));
  return d;
}
__device__ __forceinline__ u64 ldu64(const float2* p) {
  return *reinterpret_cast<const u64*>(p);
}
// one LDS.128 -> two u64 pairs
__device__ __forceinline__ ulonglong2 ldu128(const float4* p) {
  return *reinterpret_cast<const ulonglong2*>(p);
}

// ---------------- BN folding into next linear ----------------
// wq layout: wq[j*4 + q] = float4 of W'[4q..4q+3][j]  (column j, outputs 4q..4q+3)
__device__ void fold_bn_layer16(int stage, float invN,
                                const float* bng, const float* bnb,
                                const float* w, const float* bias,
                                float* ss, float4* wq, float2* fbp) {
  int t = threadIdx.x;
  if (t < 16) {
    float m = g_stats[stage][t] * invN;
    float var = fmaf(-m, m, g_stats[stage][16 + t] * invN);
    float scale = rsqrtf(var + EPSBN) * bng[t];
    ss[t] = scale;
    ss[16 + t] = bnb[t] - m * scale;
  }
  __syncthreads();
  if (t < 64) {
    int j = t >> 2, q = t & 3;
    float s = ss[j];
    wq[j * 4 + q] = make_float4(w[(4 * q) * 16 + j] * s, w[(4 * q + 1) * 16 + j] * s,
                                w[(4 * q + 2) * 16 + j] * s, w[(4 * q + 3) * 16 + j] * s);
  }
  if (t >= 64 && t < 72) {
    int p = t - 64;
    float a0 = bias[2 * p], a1 = bias[2 * p + 1];
#pragma unroll
    for (int j = 0; j < 16; j++) {
      float shj = ss[16 + j];
      a0 = fmaf(w[(2 * p) * 16 + j], shj, a0);
      a1 = fmaf(w[(2 * p + 1) * 16 + j], shj, a1);
    }
    fbp[p] = make_float2(a0, a1);
  }
}

__device__ void fold_bn_layer1(float invN,
                               const float* bng, const float* bnb,
                               const float* w1, const float* b1,
                               float* ss, float2* w1p, float2* fb1p) {
  int t = threadIdx.x;
  if (t < 2) {
    float m = g_stats[0][t] * invN;
    float var = fmaf(-m, m, g_stats[0][16 + t] * invN);
    float scale = rsqrtf(var + EPSBN) * bng[t];
    ss[t] = scale;
    ss[2 + t] = bnb[t] - m * scale;
  }
  __syncthreads();
  if (t >= 128 && t < 144) {
    int e = t - 128;
    int j = e >> 3, p = e & 7;
    float s = ss[j];
    w1p[j * 8 + p] = make_float2(w1[(2 * p) * 2 + j] * s, w1[(2 * p + 1) * 2 + j] * s);
  }
  if (t >= 144 && t < 152) {
    int p = t - 144;
    float a0 = fmaf(w1[(2 * p) * 2 + 0], ss[2], fmaf(w1[(2 * p) * 2 + 1], ss[3], b1[2 * p]));
    float a1 = fmaf(w1[(2 * p + 1) * 2 + 0], ss[2], fmaf(w1[(2 * p + 1) * 2 + 1], ss[3], b1[2 * p + 1]));
    fb1p[p] = make_float2(a0, a1);
  }
}

// ---------------- per-row layers ----------------
__device__ __forceinline__ void compute_h1(const float2* w1p, const float2* fb1p,
                                           float x0, float x1, float (&h)[16]) {
  u64 v0 = pack2(x0, x0), v1 = pack2(x1, x1);
#pragma unroll
  for (int p = 0; p < 8; p++) {
    u64 a = ldu64(&fb1p[p]);
    a = fma2(ldu64(&w1p[p]), v0, a);
    a = fma2(ldu64(&w1p[8 + p]), v1, a);
    float lo, hi; unpack2(a, lo, hi);
    h[2 * p] = fmaxf(lo, 0.f);
    h[2 * p + 1] = fmaxf(hi, 0.f);
  }
}

// single-row 16x16 layer, LDS.128 weight loads
__device__ __forceinline__ void layer16(const float4* wq, const float2* fbp,
                                        const float (&v)[16], float (&o)[16]) {
  u64 acc[8];
#pragma unroll
  for (int p = 0; p < 8; p++) acc[p] = ldu64(&fbp[p]);
#pragma unroll
  for (int j = 0; j < 16; j++) {
    u64 vr = pack2(v[j], v[j]);
#pragma unroll
    for (int q = 0; q < 4; q++) {
      ulonglong2 w = ldu128(&wq[j * 4 + q]);
      acc[2 * q] = fma2(w.x, vr, acc[2 * q]);
      acc[2 * q + 1] = fma2(w.y, vr, acc[2 * q + 1]);
    }
  }
#pragma unroll
  for (int p = 0; p < 8; p++) {
    float a, b; unpack2(acc[p], a, b);
    o[2 * p] = fmaxf(a, 0.f);
    o[2 * p + 1] = fmaxf(b, 0.f);
  }
}

__device__ __forceinline__ void load_h2(int row, float (&h)[16]) {
#pragma unroll
  for (int p = 0; p < 4; p++) {
    float4 f = g_h2[p * CAP + row];
    h[4 * p] = f.x; h[4 * p + 1] = f.y; h[4 * p + 2] = f.z; h[4 * p + 3] = f.w;
  }
}

__device__ __forceinline__ void stats_add(const float (&h)[16], u64 (&sum2)[8], u64 (&sq2)[8]) {
#pragma unroll
  for (int p = 0; p < 8; p++) {
    u64 hp = pack2(h[2 * p], h[2 * p + 1]);
    sum2[p] = add2(sum2[p], hp);
    sq2[p] = fma2(hp, hp, sq2[p]);
  }
}

__device__ void stats_flush(int stage, float* sAcc, u64 (&sum2)[8], u64 (&sq2)[8]) {
#pragma unroll
  for (int p = 0; p < 8; p++) {
#pragma unroll
    for (int o = 16; o > 0; o >>= 1) {
      sum2[p] = add2(sum2[p], __shfl_xor_sync(0xffffffffu, sum2[p], o));
      sq2[p] = add2(sq2[p], __shfl_xor_sync(0xffffffffu, sq2[p], o));
    }
    if ((threadIdx.x & 31) == 0) {
      float a, b;
      unpack2(sum2[p], a, b);
      atomicAdd(&sAcc[2 * p], a); atomicAdd(&sAcc[2 * p + 1], b);
      unpack2(sq2[p], a, b);
      atomicAdd(&sAcc[16 + 2 * p], a); atomicAdd(&sAcc[16 + 2 * p + 1], b);
    }
  }
  __syncthreads();
  if (threadIdx.x < 32) atomicAdd(&g_stats[stage][threadIdx.x], sAcc[threadIdx.x]);
}

// ---------------- K0 ----------------
__global__ void k_setup(const float* __restrict__ emb, const float* __restrict__ wc,
                        const float* __restrict__ bc) {
  int t = threadIdx.x;  // 512
  if (t < 160) ((float*)g_stats)[t] = 0.f;
  int p = t >> 6, u = t & 63;
  float a = bc[u];
#pragma unroll
  for (int k = 0; k < 16; k++) a = fmaf(emb[p * 16 + k], wc[u * 32 + 16 + k], a);
  g_ctab[t] = a;
}

// ---------------- K1 ----------------
__global__ void __launch_bounds__(256, 2) k_stats0(const float2* __restrict__ x, int n) {
  __shared__ float sAcc[4];
  if (threadIdx.x < 4) sAcc[threadIdx.x] = 0.f;
  __syncthreads();
  float s0 = 0.f, s1 = 0.f, q0 = 0.f, q1 = 0.f;
  int stride = gridDim.x * blockDim.x;
  for (int i = blockIdx.x * blockDim.x + threadIdx.x; i < n; i += stride) {
    float2 v = x[i];
    s0 += v.x; s1 += v.y;
    q0 = fmaf(v.x, v.x, q0); q1 = fmaf(v.y, v.y, q1);
  }
#pragma unroll
  for (int o = 16; o > 0; o >>= 1) {
    s0 += __shfl_xor_sync(0xffffffffu, s0, o);
    s1 += __shfl_xor_sync(0xffffffffu, s1, o);
    q0 += __shfl_xor_sync(0xffffffffu, q0, o);
    q1 += __shfl_xor_sync(0xffffffffu, q1, o);
  }
  if ((threadIdx.x & 31) == 0) {
    atomicAdd(&sAcc[0], s0); atomicAdd(&sAcc[1], s1);
    atomicAdd(&sAcc[2], q0); atomicAdd(&sAcc[3], q1);
  }
  __syncthreads();
  if (threadIdx.x < 2) {
    atomicAdd(&g_stats[0][threadIdx.x], sAcc[threadIdx.x]);
    atomicAdd(&g_stats[0][16 + threadIdx.x], sAcc[2 + threadIdx.x]);
  }
}

// ---------------- K2: h1, stats1 ----------------
__global__ void __launch_bounds__(256, 2) k_pass2(
    const float2* __restrict__ x, int n,
    const float* __restrict__ bn0g, const float* __restrict__ bn0b,
    const float* __restrict__ w1, const float* __restrict__ b1) {
  __shared__ float ss0[4];
  __shared__ float2 w1p[16], fb1p[8];
  __shared__ float sAcc[32];
  if (threadIdx.x < 32) sAcc[threadIdx.x] = 0.f;
  float invN = 1.0f / (float)n;
  fold_bn_layer1(invN, bn0g, bn0b, w1, b1, ss0, w1p, fb1p);
  __syncthreads();

  u64 sum2[8], sq2[8];
#pragma unroll
  for (int p = 0; p < 8; p++) { sum2[p] = 0ull; sq2[p] = 0ull; }
  int stride = gridDim.x * blockDim.x;
  for (int i = blockIdx.x * blockDim.x + threadIdx.x; i < n; i += stride) {
    float2 xv = x[i];
    float h[16];
    compute_h1(w1p, fb1p, xv.x, xv.y, h);
    stats_add(h, sum2, sq2);
  }
  stats_flush(1, sAcc, sum2, sq2);
}

// ---------------- K3: y1a, stats2 ----------------
__global__ void __launch_bounds__(256, 2) k_pass3(
    const float2* __restrict__ x, int n,
    const float* __restrict__ bn0g, const float* __restrict__ bn0b,
    const float* __restrict__ bn1g, const float* __restrict__ bn1b,
    const float* __restrict__ w1, const float* __restrict__ b1,
    const float* __restrict__ w2, const float* __restrict__ b2) {
  __shared__ float ss0[4];  __shared__ float2 w1p[16], fb1p[8];
  __shared__ float ss1[32]; __shared__ float4 w2q[64]; __shared__ float2 fb2p[8];
  __shared__ float sAcc[32];
  if (threadIdx.x < 32) sAcc[threadIdx.x] = 0.f;
  float invN = 1.0f / (float)n;
  fold_bn_layer1(invN, bn0g, bn0b, w1, b1, ss0, w1p, fb1p);
  fold_bn_layer16(1, invN, bn1g, bn1b, w2, b2, ss1, w2q, fb2p);
  __syncthreads();

  u64 sum2[8], sq2[8];
#pragma unroll
  for (int p = 0; p < 8; p++) { sum2[p] = 0ull; sq2[p] = 0ull; }
  int stride = gridDim.x * blockDim.x;
  for (int i = blockIdx.x * blockDim.x + threadIdx.x; i < n; i += stride) {
    float2 xv = x[i];
    float h[16], y[16];
    compute_h1(w1p, fb1p, xv.x, xv.y, h);
    layer16(w2q, fb2p, h, y);
    stats_add(y, sum2, sq2);
  }
  stats_flush(2, sAcc, sum2, sq2);
}

// ---------------- K4: h2 = h1 + L3(BN2 y1a); store; stats3 ----------------
__global__ void __launch_bounds__(256, 2) k_pass4(
    const float2* __restrict__ x, int n,
    const float* __restrict__ bn0g, const float* __restrict__ bn0b,
    const float* __restrict__ bn1g, const float* __restrict__ bn1b,
    const float* __restrict__ bn2g, const float* __restrict__ bn2b,
    const float* __restrict__ w1, const float* __restrict__ b1,
    const float* __restrict__ w2, const float* __restrict__ b2,
    const float* __restrict__ w3, const float* __restrict__ b3) {
  __shared__ float ss0[4];  __shared__ float2 w1p[16], fb1p[8];
  __shared__ float ss1[32]; __shared__ float4 w2q[64]; __shared__ float2 fb2p[8];
  __shared__ float ss2[32]; __shared__ float4 w3q[64]; __shared__ float2 fb3p[8];
  __shared__ float sAcc[32];
  if (threadIdx.x < 32) sAcc[threadIdx.x] = 0.f;
  float invN = 1.0f / (float)n;
  fold_bn_layer1(invN, bn0g, bn0b, w1, b1, ss0, w1p, fb1p);
  fold_bn_layer16(1, invN, bn1g, bn1b, w2, b2, ss1, w2q, fb2p);
  fold_bn_layer16(2, invN, bn2g, bn2b, w3, b3, ss2, w3q, fb3p);
  __syncthreads();

  u64 sum2[8], sq2[8];
#pragma unroll
  for (int p = 0; p < 8; p++) { sum2[p] = 0ull; sq2[p] = 0ull; }
  int stride = gridDim.x * blockDim.x;
  for (int i = blockIdx.x * blockDim.x + threadIdx.x; i < n; i += stride) {
    float2 xv = x[i];
    float h[16], y[16], z[16];
    compute_h1(w1p, fb1p, xv.x, xv.y, h);
    layer16(w2q, fb2p, h, y);
    layer16(w3q, fb3p, y, z);
#pragma unroll
    for (int c = 0; c < 16; c++) h[c] += z[c];   // h2
#pragma unroll
    for (int p = 0; p < 4; p++)
      g_h2[p * CAP + i] = make_float4(h[4 * p], h[4 * p + 1], h[4 * p + 2], h[4 * p + 3]);
    stats_add(h, sum2, sq2);
  }
  stats_flush(3, sAcc, sum2, sq2);
}

// ---------------- K5: y2a, stats4 ----------------
__global__ void __launch_bounds__(256, 2) k_pass5(
    int n,
    const float* __restrict__ bn3g, const float* __restrict__ bn3b,
    const float* __restrict__ w4, const float* __restrict__ b4) {
  __shared__ float ss3[32]; __shared__ float4 w4q[64]; __shared__ float2 fb4p[8];
  __shared__ float sAcc[32];
  if (threadIdx.x < 32) sAcc[threadIdx.x] = 0.f;
  float invN = 1.0f / (float)n;
  fold_bn_layer16(3, invN, bn3g, bn3b, w4, b4, ss3, w4q, fb4p);
  __syncthreads();

  u64 sum2[8], sq2[8];
#pragma unroll
  for (int p = 0; p < 8; p++) { sum2[p] = 0ull; sq2[p] = 0ull; }
  int stride = gridDim.x * blockDim.x;
  for (int i = blockIdx.x * blockDim.x + threadIdx.x; i < n; i += stride) {
    float h[16], y[16];
    load_h2(i, h);
    layer16(w4q, fb4p, h, y);
    stats_add(y, sum2, sq2);
  }
  stats_flush(4, sAcc, sum2, sq2);
}

// ---------------- K6: final ----------------
__global__ void __launch_bounds__(256, 2) k_final(
    int n, const int* __restrict__ idx, float* __restrict__ out,
    const float* __restrict__ bn3g, const float* __restrict__ bn3b,
    const float* __restrict__ bn4g, const float* __restrict__ bn4b,
    const float* __restrict__ w4, const float* __restrict__ b4,
    const float* __restrict__ w5, const float* __restrict__ b5,
    const float* __restrict__ wc) {
  __shared__ float ss3[32]; __shared__ float4 w4q[64]; __shared__ float2 fb4p[8];
  __shared__ float ss4[32]; __shared__ float4 w5q[64]; __shared__ float2 fb5p[8];
  __shared__ float4 wc4[256];      // wc4[k*16+q] = wc_head[4q..4q+3][k]
  __shared__ float4 sct4[128];     // sct4[part*16+q] = ctab[part][4q..4q+3]
  __shared__ float2 so2[16 * 257]; // output staging, padded
  float invN = 1.0f / (float)n;
  fold_bn_layer16(3, invN, bn3g, bn3b, w4, b4, ss3, w4q, fb4p);
  fold_bn_layer16(4, invN, bn4g, bn4b, w5, b5, ss4, w5q, fb5p);
  int t = threadIdx.x;
  {
    int k = t >> 4, q = t & 15;
    wc4[t] = make_float4(wc[(4 * q) * 32 + k], wc[(4 * q + 1) * 32 + k],
                         wc[(4 * q + 2) * 32 + k], wc[(4 * q + 3) * 32 + k]);
    if (t < 128) sct4[t] = ((const float4*)g_ctab)[t];
  }
  __syncthreads();

  int blockBase = blockIdx.x * 256;
  int i = blockBase + t;
  bool valid = (i < n);

  float h3[16];
  int part = 0;
  if (valid) {
    float h[16], y[16], z[16];
    load_h2(i, h);
    layer16(w4q, fb4p, h, y);
    layer16(w5q, fb5p, y, z);
#pragma unroll
    for (int c = 0; c < 16; c++) h3[c] = h[c] + z[c];
    part = idx[i];
  } else {
#pragma unroll
    for (int c = 0; c < 16; c++) h3[c] = 0.f;
  }

  float2* o2 = (float2*)out;
#pragma unroll
  for (int half = 0; half < 2; half++) {
    u64 acc[16];
#pragma unroll
    for (int q = 0; q < 8; q++) {
      ulonglong2 c0 = ldu128(&sct4[part * 16 + half * 8 + q]);
      acc[2 * q] = c0.x; acc[2 * q + 1] = c0.y;
    }
#pragma unroll
    for (int k = 0; k < 16; k++) {
      u64 hk = pack2(h3[k], h3[k]);
#pragma unroll
      for (int q = 0; q < 8; q++) {
        ulonglong2 w = ldu128(&wc4[k * 16 + half * 8 + q]);
        acc[2 * q] = fma2(w.x, hk, acc[2 * q]);
        acc[2 * q + 1] = fma2(w.y, hk, acc[2 * q + 1]);
      }
    }
#pragma unroll
    for (int p = 0; p < 16; p++)
      *reinterpret_cast<u64*>(&so2[p * 257 + t]) = acc[p];
    __syncthreads();
#pragma unroll
    for (int q = 0; q < 16; q++) {
      int li = q * 256 + t;
      int r = li >> 4, p = li & 15;
      int row = blockBase + r;
      if (row < n) o2[(size_t)row * 32 + half * 16 + p] = so2[p * 257 + r];
    }
    __syncthreads();
  }
}

// ---------------- launch ----------------
extern "C" void kernel_launch(void* const* d_in, const int* in_sizes, int n_in,
                              void* d_out, int out_size) {
  const float2* x  = (const float2*)d_in[0];
  const int* idx   = (const int*)d_in[1];
  const float* bn0g = (const float*)d_in[2],  *bn0b = (const float*)d_in[3];
  const float* bn1g = (const float*)d_in[4],  *bn1b = (const float*)d_in[5];
  const float* bn2g = (const float*)d_in[6],  *bn2b = (const float*)d_in[7];
  const float* bn3g = (const float*)d_in[8],  *bn3b = (const float*)d_in[9];
  const float* bn4g = (const float*)d_in[10], *bn4b = (const float*)d_in[11];
  const float* w1 = (const float*)d_in[12], *b1 = (const float*)d_in[13];
  const float* w2 = (const float*)d_in[14], *b2 = (const float*)d_in[15];
  const float* w3 = (const float*)d_in[16], *b3 = (const float*)d_in[17];
  const float* w4 = (const float*)d_in[18], *b4 = (const float*)d_in[19];
  const float* w5 = (const float*)d_in[20], *b5 = (const float*)d_in[21];
  const float* emb = (const float*)d_in[22];
  const float* wc  = (const float*)d_in[23], *bc = (const float*)d_in[24];
  float* out = (float*)d_out;
  int n = in_sizes[1];

  k_setup<<<1, 512>>>(emb, wc, bc);
  k_stats0<<<SGRID, 256>>>(x, n);
  k_pass2<<<SGRID, 256>>>(x, n, bn0g, bn0b, w1, b1);
  k_pass3<<<SGRID, 256>>>(x, n, bn0g, bn0b, bn1g, bn1b, w1, b1, w2, b2);
  k_pass4<<<SGRID, 256>>>(x, n, bn0g, bn0b, bn1g, bn1b, bn2g, bn2b, w1, b1, w2, b2, w3, b3);
  k_pass5<<<SGRID, 256>>>(n, bn3g, bn3b, w4, b4);
  k_final<<<(n + 255) / 256, 256>>>(n, idx, out, bn3g, bn3b, bn4g, bn4b, w4, b4, w5, b5, wc);
}

// round 11
// speedup vs baseline: 1.1922x; 1.1922x over previous
#include <cuda_runtime.h>

typedef unsigned long long u64;
typedef unsigned int u32;

#define CAP 2097152
#define EPSBN 1e-5f
#define SGRID 2368
#define TB 128

__device__ float4 g_h2[4 * CAP];                    // h2 plane-major: [plane p][row]
__device__ float g_stats[5][32];                    // [stage][sum 0..15 | sumsq 0..15]
__device__ __align__(16) float g_ctab[8 * 64];      // emb@wc_tail^T + bc

// ---------------- packed f32x2 helpers ----------------
__device__ __forceinline__ u64 pack2(float x, float y) {
  u64 d;
  asm("mov.b64 %0, {%1, %2};" : "=l"(d) : "r"(__float_as_uint(x)), "r"(__float_as_uint(y)));
  return d;
}
__device__ __forceinline__ void unpack2(u64 a, float& x, float& y) {
  u32 lo, hi;
  asm("mov.b64 {%0, %1}, %2;" : "=r"(lo), "=r"(hi) : "l"(a));
  x = __uint_as_float(lo); y = __uint_as_float(hi);
}
__device__ __forceinline__ u64 fma2(u64 a, u64 b, u64 c) {
  u64 d;
  asm("fma.rn.f32x2 %0, %1, %2, %3;" : "=l"(d) : "l"(a), "l"(b), "l"(c));
  return d;
}
__device__ __forceinline__ u64 add2(u64 a, u64 b) {
  u64 d;
  asm("add.rn.f32x2 %0, %1, %2;" : "=l"(d) : "l"(a), "l"(b));
  return d;
}
__device__ __forceinline__ u64 ldu64(const float2* p) {
  return *reinterpret_cast<const u64*>(p);
}
__device__ __forceinline__ ulonglong2 ldu128(const float4* p) {
  return *reinterpret_cast<const ulonglong2*>(p);
}

// ---------------- BN folding into next linear (block of 128 threads) ----------------
// wq layout: wq[j*4 + q] = float4 of W'[4q..4q+3][j]
__device__ void fold_bn_layer16(int stage, float invN,
                                const float* bng, const float* bnb,
                                const float* w, const float* bias,
                                float* ss, float4* wq, float2* fbp) {
  int t = threadIdx.x;
  if (t < 16) {
    float m = g_stats[stage][t] * invN;
    float var = fmaf(-m, m, g_stats[stage][16 + t] * invN);
    float scale = rsqrtf(var + EPSBN) * bng[t];
    ss[t] = scale;
    ss[16 + t] = bnb[t] - m * scale;
  }
  __syncthreads();
  if (t < 64) {
    int j = t >> 2, q = t & 3;
    float s = ss[j];
    wq[j * 4 + q] = make_float4(w[(4 * q) * 16 + j] * s, w[(4 * q + 1) * 16 + j] * s,
                                w[(4 * q + 2) * 16 + j] * s, w[(4 * q + 3) * 16 + j] * s);
  }
  if (t >= 64 && t < 72) {
    int p = t - 64;
    float a0 = bias[2 * p], a1 = bias[2 * p + 1];
#pragma unroll
    for (int j = 0; j < 16; j++) {
      float shj = ss[16 + j];
      a0 = fmaf(w[(2 * p) * 16 + j], shj, a0);
      a1 = fmaf(w[(2 * p + 1) * 16 + j], shj, a1);
    }
    fbp[p] = make_float2(a0, a1);
  }
}

__device__ void fold_bn_layer1(float invN,
                               const float* bng, const float* bnb,
                               const float* w1, const float* b1,
                               float* ss, float2* w1p, float2* fb1p) {
  int t = threadIdx.x;
  if (t < 2) {
    float m = g_stats[0][t] * invN;
    float var = fmaf(-m, m, g_stats[0][16 + t] * invN);
    float scale = rsqrtf(var + EPSBN) * bng[t];
    ss[t] = scale;
    ss[2 + t] = bnb[t] - m * scale;
  }
  __syncthreads();
  if (t >= 96 && t < 112) {
    int e = t - 96;
    int j = e >> 3, p = e & 7;
    float s = ss[j];
    w1p[j * 8 + p] = make_float2(w1[(2 * p) * 2 + j] * s, w1[(2 * p + 1) * 2 + j] * s);
  }
  if (t >= 112 && t < 120) {
    int p = t - 112;
    float a0 = fmaf(w1[(2 * p) * 2 + 0], ss[2], fmaf(w1[(2 * p) * 2 + 1], ss[3], b1[2 * p]));
    float a1 = fmaf(w1[(2 * p + 1) * 2 + 0], ss[2], fmaf(w1[(2 * p + 1) * 2 + 1], ss[3], b1[2 * p + 1]));
    fb1p[p] = make_float2(a0, a1);
  }
}

// ---------------- per-row layers ----------------
__device__ __forceinline__ void compute_h1(const float2* w1p, const float2* fb1p,
                                           float x0, float x1, float (&h)[16]) {
  u64 v0 = pack2(x0, x0), v1 = pack2(x1, x1);
#pragma unroll
  for (int p = 0; p < 8; p++) {
    u64 a = ldu64(&fb1p[p]);
    a = fma2(ldu64(&w1p[p]), v0, a);
    a = fma2(ldu64(&w1p[8 + p]), v1, a);
    float lo, hi; unpack2(a, lo, hi);
    h[2 * p] = fmaxf(lo, 0.f);
    h[2 * p + 1] = fmaxf(hi, 0.f);
  }
}

__device__ __forceinline__ void layer16(const float4* wq, const float2* fbp,
                                        const float (&v)[16], float (&o)[16]) {
  u64 acc[8];
#pragma unroll
  for (int p = 0; p < 8; p++) acc[p] = ldu64(&fbp[p]);
#pragma unroll
  for (int j = 0; j < 16; j++) {
    u64 vr = pack2(v[j], v[j]);
#pragma unroll
    for (int q = 0; q < 4; q++) {
      ulonglong2 w = ldu128(&wq[j * 4 + q]);
      acc[2 * q] = fma2(w.x, vr, acc[2 * q]);
      acc[2 * q + 1] = fma2(w.y, vr, acc[2 * q + 1]);
    }
  }
#pragma unroll
  for (int p = 0; p < 8; p++) {
    float a, b; unpack2(acc[p], a, b);
    o[2 * p] = fmaxf(a, 0.f);
    o[2 * p + 1] = fmaxf(b, 0.f);
  }
}

__device__ __forceinline__ void load_h2(int row, float (&h)[16]) {
#pragma unroll
  for (int p = 0; p < 4; p++) {
    float4 f = g_h2[p * CAP + row];
    h[4 * p] = f.x; h[4 * p + 1] = f.y; h[4 * p + 2] = f.z; h[4 * p + 3] = f.w;
  }
}

__device__ __forceinline__ void stats_add(const float (&h)[16], u64 (&sum2)[8], u64 (&sq2)[8]) {
#pragma unroll
  for (int p = 0; p < 8; p++) {
    u64 hp = pack2(h[2 * p], h[2 * p + 1]);
    sum2[p] = add2(sum2[p], hp);
    sq2[p] = fma2(hp, hp, sq2[p]);
  }
}

__device__ void stats_flush(int stage, float* sAcc, u64 (&sum2)[8], u64 (&sq2)[8]) {
#pragma unroll
  for (int p = 0; p < 8; p++) {
#pragma unroll
    for (int o = 16; o > 0; o >>= 1) {
      sum2[p] = add2(sum2[p], __shfl_xor_sync(0xffffffffu, sum2[p], o));
      sq2[p] = add2(sq2[p], __shfl_xor_sync(0xffffffffu, sq2[p], o));
    }
    if ((threadIdx.x & 31) == 0) {
      float a, b;
      unpack2(sum2[p], a, b);
      atomicAdd(&sAcc[2 * p], a); atomicAdd(&sAcc[2 * p + 1], b);
      unpack2(sq2[p], a, b);
      atomicAdd(&sAcc[16 + 2 * p], a); atomicAdd(&sAcc[16 + 2 * p + 1], b);
    }
  }
  __syncthreads();
  if (threadIdx.x < 32) atomicAdd(&g_stats[stage][threadIdx.x], sAcc[threadIdx.x]);
}

// ---------------- K0 ----------------
__global__ void k_setup(const float* __restrict__ emb, const float* __restrict__ wc,
                        const float* __restrict__ bc) {
  int t = threadIdx.x;  // 512
  if (t < 160) ((float*)g_stats)[t] = 0.f;
  int p = t >> 6, u = t & 63;
  float a = bc[u];
#pragma unroll
  for (int k = 0; k < 16; k++) a = fmaf(emb[p * 16 + k], wc[u * 32 + 16 + k], a);
  g_ctab[t] = a;
}

// ---------------- K1 ----------------
__global__ void __launch_bounds__(TB, 3) k_stats0(const float2* __restrict__ x, int n) {
  __shared__ float sAcc[4];
  if (threadIdx.x < 4) sAcc[threadIdx.x] = 0.f;
  __syncthreads();
  float s0 = 0.f, s1 = 0.f, q0 = 0.f, q1 = 0.f;
  int stride = gridDim.x * blockDim.x;
  for (int i = blockIdx.x * blockDim.x + threadIdx.x; i < n; i += stride) {
    float2 v = x[i];
    s0 += v.x; s1 += v.y;
    q0 = fmaf(v.x, v.x, q0); q1 = fmaf(v.y, v.y, q1);
  }
#pragma unroll
  for (int o = 16; o > 0; o >>= 1) {
    s0 += __shfl_xor_sync(0xffffffffu, s0, o);
    s1 += __shfl_xor_sync(0xffffffffu, s1, o);
    q0 += __shfl_xor_sync(0xffffffffu, q0, o);
    q1 += __shfl_xor_sync(0xffffffffu, q1, o);
  }
  if ((threadIdx.x & 31) == 0) {
    atomicAdd(&sAcc[0], s0); atomicAdd(&sAcc[1], s1);
    atomicAdd(&sAcc[2], q0); atomicAdd(&sAcc[3], q1);
  }
  __syncthreads();
  if (threadIdx.x < 2) {
    atomicAdd(&g_stats[0][threadIdx.x], sAcc[threadIdx.x]);
    atomicAdd(&g_stats[0][16 + threadIdx.x], sAcc[2 + threadIdx.x]);
  }
}

// ---------------- K2: h1, stats1 ----------------
__global__ void __launch_bounds__(TB, 3) k_pass2(
    const float2* __restrict__ x, int n,
    const float* __restrict__ bn0g, const float* __restrict__ bn0b,
    const float* __restrict__ w1, const float* __restrict__ b1) {
  __shared__ float ss0[4];
  __shared__ float2 w1p[16], fb1p[8];
  __shared__ float sAcc[32];
  if (threadIdx.x < 32) sAcc[threadIdx.x] = 0.f;
  float invN = 1.0f / (float)n;
  fold_bn_layer1(invN, bn0g, bn0b, w1, b1, ss0, w1p, fb1p);
  __syncthreads();

  u64 sum2[8], sq2[8];
#pragma unroll
  for (int p = 0; p < 8; p++) { sum2[p] = 0ull; sq2[p] = 0ull; }
  int stride = gridDim.x * blockDim.x;
  for (int i = blockIdx.x * blockDim.x + threadIdx.x; i < n; i += stride) {
    float2 xv = x[i];
    float h[16];
    compute_h1(w1p, fb1p, xv.x, xv.y, h);
    stats_add(h, sum2, sq2);
  }
  stats_flush(1, sAcc, sum2, sq2);
}

// ---------------- K3: y1a, stats2 ----------------
__global__ void __launch_bounds__(TB, 3) k_pass3(
    const float2* __restrict__ x, int n,
    const float* __restrict__ bn0g, const float* __restrict__ bn0b,
    const float* __restrict__ bn1g, const float* __restrict__ bn1b,
    const float* __restrict__ w1, const float* __restrict__ b1,
    const float* __restrict__ w2, const float* __restrict__ b2) {
  __shared__ float ss0[4];  __shared__ float2 w1p[16], fb1p[8];
  __shared__ float ss1[32]; __shared__ float4 w2q[64]; __shared__ float2 fb2p[8];
  __shared__ float sAcc[32];
  if (threadIdx.x < 32) sAcc[threadIdx.x] = 0.f;
  float invN = 1.0f / (float)n;
  fold_bn_layer1(invN, bn0g, bn0b, w1, b1, ss0, w1p, fb1p);
  fold_bn_layer16(1, invN, bn1g, bn1b, w2, b2, ss1, w2q, fb2p);
  __syncthreads();

  u64 sum2[8], sq2[8];
#pragma unroll
  for (int p = 0; p < 8; p++) { sum2[p] = 0ull; sq2[p] = 0ull; }
  int stride = gridDim.x * blockDim.x;
  for (int i = blockIdx.x * blockDim.x + threadIdx.x; i < n; i += stride) {
    float2 xv = x[i];
    float h[16], y[16];
    compute_h1(w1p, fb1p, xv.x, xv.y, h);
    layer16(w2q, fb2p, h, y);
    stats_add(y, sum2, sq2);
  }
  stats_flush(2, sAcc, sum2, sq2);
}

// ---------------- K4: h2 = h1 + L3(BN2 y1a); store; stats3 ----------------
__global__ void __launch_bounds__(TB, 3) k_pass4(
    const float2* __restrict__ x, int n,
    const float* __restrict__ bn0g, const float* __restrict__ bn0b,
    const float* __restrict__ bn1g, const float* __restrict__ bn1b,
    const float* __restrict__ bn2g, const float* __restrict__ bn2b,
    const float* __restrict__ w1, const float* __restrict__ b1,
    const float* __restrict__ w2, const float* __restrict__ b2,
    const float* __restrict__ w3, const float* __restrict__ b3) {
  __shared__ float ss0[4];  __shared__ float2 w1p[16], fb1p[8];
  __shared__ float ss1[32]; __shared__ float4 w2q[64]; __shared__ float2 fb2p[8];
  __shared__ float ss2[32]; __shared__ float4 w3q[64]; __shared__ float2 fb3p[8];
  __shared__ float sAcc[32];
  if (threadIdx.x < 32) sAcc[threadIdx.x] = 0.f;
  float invN = 1.0f / (float)n;
  fold_bn_layer1(invN, bn0g, bn0b, w1, b1, ss0, w1p, fb1p);
  fold_bn_layer16(1, invN, bn1g, bn1b, w2, b2, ss1, w2q, fb2p);
  fold_bn_layer16(2, invN, bn2g, bn2b, w3, b3, ss2, w3q, fb3p);
  __syncthreads();

  u64 sum2[8], sq2[8];
#pragma unroll
  for (int p = 0; p < 8; p++) { sum2[p] = 0ull; sq2[p] = 0ull; }
  int stride = gridDim.x * blockDim.x;
  for (int i = blockIdx.x * blockDim.x + threadIdx.x; i < n; i += stride) {
    float2 xv = x[i];
    float h[16], y[16], z[16];
    compute_h1(w1p, fb1p, xv.x, xv.y, h);
    layer16(w2q, fb2p, h, y);
    layer16(w3q, fb3p, y, z);
#pragma unroll
    for (int c = 0; c < 16; c++) h[c] += z[c];   // h2
#pragma unroll
    for (int p = 0; p < 4; p++)
      g_h2[p * CAP + i] = make_float4(h[4 * p], h[4 * p + 1], h[4 * p + 2], h[4 * p + 3]);
    stats_add(h, sum2, sq2);
  }
  stats_flush(3, sAcc, sum2, sq2);
}

// ---------------- K5: y2a, stats4 ----------------
__global__ void __launch_bounds__(TB, 3) k_pass5(
    int n,
    const float* __restrict__ bn3g, const float* __restrict__ bn3b,
    const float* __restrict__ w4, const float* __restrict__ b4) {
  __shared__ float ss3[32]; __shared__ float4 w4q[64]; __shared__ float2 fb4p[8];
  __shared__ float sAcc[32];
  if (threadIdx.x < 32) sAcc[threadIdx.x] = 0.f;
  float invN = 1.0f / (float)n;
  fold_bn_layer16(3, invN, bn3g, bn3b, w4, b4, ss3, w4q, fb4p);
  __syncthreads();

  u64 sum2[8], sq2[8];
#pragma unroll
  for (int p = 0; p < 8; p++) { sum2[p] = 0ull; sq2[p] = 0ull; }
  int stride = gridDim.x * blockDim.x;
  for (int i = blockIdx.x * blockDim.x + threadIdx.x; i < n; i += stride) {
    float h[16], y[16];
    load_h2(i, h);
    layer16(w4q, fb4p, h, y);
    stats_add(y, sum2, sq2);
  }
  stats_flush(4, sAcc, sum2, sq2);
}

// ---------------- K6: final ----------------
__global__ void __launch_bounds__(TB, 3) k_final(
    int n, const int* __restrict__ idx, float* __restrict__ out,
    const float* __restrict__ bn3g, const float* __restrict__ bn3b,
    const float* __restrict__ bn4g, const float* __restrict__ bn4b,
    const float* __restrict__ w4, const float* __restrict__ b4,
    const float* __restrict__ w5, const float* __restrict__ b5,
    const float* __restrict__ wc) {
  __shared__ float ss3[32]; __shared__ float4 w4q[64]; __shared__ float2 fb4p[8];
  __shared__ float ss4[32]; __shared__ float4 w5q[64]; __shared__ float2 fb5p[8];
  __shared__ float4 wc4[256];      // wc4[k*16+q] = wc_head[4q..4q+3][k]
  __shared__ float4 sct4[128];     // sct4[part*16+q] = ctab[part][4q..4q+3]
  __shared__ float2 so2[16 * 129]; // output staging (128 rows), padded
  float invN = 1.0f / (float)n;
  fold_bn_layer16(3, invN, bn3g, bn3b, w4, b4, ss3, w4q, fb4p);
  fold_bn_layer16(4, invN, bn4g, bn4b, w5, b5, ss4, w5q, fb5p);
  int t = threadIdx.x;
  {
#pragma unroll
    for (int e = t; e < 256; e += TB) {
      int k = e >> 4, q = e & 15;
      wc4[e] = make_float4(wc[(4 * q) * 32 + k], wc[(4 * q + 1) * 32 + k],
                           wc[(4 * q + 2) * 32 + k], wc[(4 * q + 3) * 32 + k]);
    }
    sct4[t] = ((const float4*)g_ctab)[t];
  }
  __syncthreads();

  int blockBase = blockIdx.x * TB;
  int i = blockBase + t;
  bool valid = (i < n);

  float h3[16];
  int part = 0;
  if (valid) {
    float h[16], y[16], z[16];
    load_h2(i, h);
    layer16(w4q, fb4p, h, y);
    layer16(w5q, fb5p, y, z);
#pragma unroll
    for (int c = 0; c < 16; c++) h3[c] = h[c] + z[c];
    part = idx[i];
  } else {
#pragma unroll
    for (int c = 0; c < 16; c++) h3[c] = 0.f;
  }

  float2* o2 = (float2*)out;
#pragma unroll
  for (int half = 0; half < 2; half++) {
    u64 acc[16];
#pragma unroll
    for (int q = 0; q < 8; q++) {
      ulonglong2 c0 = ldu128(&sct4[part * 16 + half * 8 + q]);
      acc[2 * q] = c0.x; acc[2 * q + 1] = c0.y;
    }
#pragma unroll
    for (int k = 0; k < 16; k++) {
      u64 hk = pack2(h3[k], h3[k]);
#pragma unroll
      for (int q = 0; q < 8; q++) {
        ulonglong2 w = ldu128(&wc4[k * 16 + half * 8 + q]);
        acc[2 * q] = fma2(w.x, hk, acc[2 * q]);
        acc[2 * q + 1] = fma2(w.y, hk, acc[2 * q + 1]);
      }
    }
#pragma unroll
    for (int p = 0; p < 16; p++)
      *reinterpret_cast<u64*>(&so2[p * 129 + t]) = acc[p];
    __syncthreads();
#pragma unroll
    for (int q = 0; q < 16; q++) {
      int li = q * TB + t;
      int r = li >> 4, p = li & 15;
      int row = blockBase + r;
      if (row < n) o2[(size_t)row * 32 + half * 16 + p] = so2[p * 129 + r];
    }
    __syncthreads();
  }
}

// ---------------- launch ----------------
extern "C" void kernel_launch(void* const* d_in, const int* in_sizes, int n_in,
                              void* d_out, int out_size) {
  const float2* x  = (const float2*)d_in[0];
  const int* idx   = (const int*)d_in[1];
  const float* bn0g = (const float*)d_in[2],  *bn0b = (const float*)d_in[3];
  const float* bn1g = (const float*)d_in[4],  *bn1b = (const float*)d_in[5];
  const float* bn2g = (const float*)d_in[6],  *bn2b = (const float*)d_in[7];
  const float* bn3g = (const float*)d_in[8],  *bn3b = (const float*)d_in[9];
  const float* bn4g = (const float*)d_in[10], *bn4b = (const float*)d_in[11];
  const float* w1 = (const float*)d_in[12], *b1 = (const float*)d_in[13];
  const float* w2 = (const float*)d_in[14], *b2 = (const float*)d_in[15];
  const float* w3 = (const float*)d_in[16], *b3 = (const float*)d_in[17];
  const float* w4 = (const float*)d_in[18], *b4 = (const float*)d_in[19];
  const float* w5 = (const float*)d_in[20], *b5 = (const float*)d_in[21];
  const float* emb = (const float*)d_in[22];
  const float* wc  = (const float*)d_in[23], *bc = (const float*)d_in[24];
  float* out = (float*)d_out;
  int n = in_sizes[1];

  k_setup<<<1, 512>>>(emb, wc, bc);
  k_stats0<<<SGRID, TB>>>(x, n);
  k_pass2<<<SGRID, TB>>>(x, n, bn0g, bn0b, w1, b1);
  k_pass3<<<SGRID, TB>>>(x, n, bn0g, bn0b, bn1g, bn1b, w1, b1, w2, b2);
  k_pass4<<<SGRID, TB>>>(x, n, bn0g, bn0b, bn1g, bn1b, bn2g, bn2b, w1, b1, w2, b2, w3, b3);
  k_pass5<<<SGRID, TB>>>(n, bn3g, bn3b, w4, b4);
  k_final<<<(n + TB - 1) / TB, TB>>>(n, idx, out, bn3g, bn3b, bn4g, bn4b, w4, b4, w5, b5, wc);
}

// round 13
// speedup vs baseline: 2.2860x; 1.9175x over previous
#include <cuda_runtime.h>

typedef unsigned long long u64;
typedef unsigned int u32;

#define CAP 2097152
#define EPSBN 1e-5f
#define SGRID 1184
#define TB 256

__device__ float4 g_h2[4 * CAP];                    // h2 plane-major: [plane p][row]
__device__ float g_stats[5][32];                    // [stage][sum 0..15 | sumsq 0..15]
__device__ __align__(16) float g_ctab[8 * 64];      // emb@wc_tail^T + bc

// ---------------- packed f32x2 helpers ----------------
__device__ __forceinline__ u64 pack2(float x, float y) {
  u64 d;
  asm("mov.b64 %0, {%1, %2};" : "=l"(d) : "r"(__float_as_uint(x)), "r"(__float_as_uint(y)));
  return d;
}
__device__ __forceinline__ void unpack2(u64 a, float& x, float& y) {
  u32 lo, hi;
  asm("mov.b64 {%0, %1}, %2;" : "=r"(lo), "=r"(hi) : "l"(a));
  x = __uint_as_float(lo); y = __uint_as_float(hi);
}
__device__ __forceinline__ u64 fma2(u64 a, u64 b, u64 c) {
  u64 d;
  asm("fma.rn.f32x2 %0, %1, %2, %3;" : "=l"(d) : "l"(a), "l"(b), "l"(c));
  return d;
}
__device__ __forceinline__ u64 add2(u64 a, u64 b) {
  u64 d;
  asm("add.rn.f32x2 %0, %1, %2;" : "=l"(d) : "l"(a), "l"(b));
  return d;
}
__device__ __forceinline__ u64 ldu64(const float2* p) {
  return *reinterpret_cast<const u64*>(p);
}
__device__ __forceinline__ ulonglong2 ldu128(const float4* p) {
  return *reinterpret_cast<const ulonglong2*>(p);
}

// ---------------- BN folding into next linear (256-thread block) ----------------
// wq layout: wq[j*4 + q] = float4 of W'[4q..4q+3][j]
__device__ void fold_bn_layer16(int stage, float invN,
                                const float* bng, const float* bnb,
                                const float* w, const float* bias,
                                float* ss, float4* wq, float2* fbp) {
  int t = threadIdx.x;
  if (t < 16) {
    float m = g_stats[stage][t] * invN;
    float var = fmaf(-m, m, g_stats[stage][16 + t] * invN);
    float scale = rsqrtf(var + EPSBN) * bng[t];
    ss[t] = scale;
    ss[16 + t] = bnb[t] - m * scale;
  }
  __syncthreads();
  if (t < 64) {
    int j = t >> 2, q = t & 3;
    float s = ss[j];
    wq[j * 4 + q] = make_float4(w[(4 * q) * 16 + j] * s, w[(4 * q + 1) * 16 + j] * s,
                                w[(4 * q + 2) * 16 + j] * s, w[(4 * q + 3) * 16 + j] * s);
  }
  if (t >= 64 && t < 72) {
    int p = t - 64;
    float a0 = bias[2 * p], a1 = bias[2 * p + 1];
#pragma unroll
    for (int j = 0; j < 16; j++) {
      float shj = ss[16 + j];
      a0 = fmaf(w[(2 * p) * 16 + j], shj, a0);
      a1 = fmaf(w[(2 * p + 1) * 16 + j], shj, a1);
    }
    fbp[p] = make_float2(a0, a1);
  }
}

__device__ void fold_bn_layer1(float invN,
                               const float* bng, const float* bnb,
                               const float* w1, const float* b1,
                               float* ss, float2* w1p, float2* fb1p) {
  int t = threadIdx.x;
  if (t < 2) {
    float m = g_stats[0][t] * invN;
    float var = fmaf(-m, m, g_stats[0][16 + t] * invN);
    float scale = rsqrtf(var + EPSBN) * bng[t];
    ss[t] = scale;
    ss[2 + t] = bnb[t] - m * scale;
  }
  __syncthreads();
  if (t >= 128 && t < 144) {
    int e = t - 128;
    int j = e >> 3, p = e & 7;
    float s = ss[j];
    w1p[j * 8 + p] = make_float2(w1[(2 * p) * 2 + j] * s, w1[(2 * p + 1) * 2 + j] * s);
  }
  if (t >= 144 && t < 152) {
    int p = t - 144;
    float a0 = fmaf(w1[(2 * p) * 2 + 0], ss[2], fmaf(w1[(2 * p) * 2 + 1], ss[3], b1[2 * p]));
    float a1 = fmaf(w1[(2 * p + 1) * 2 + 0], ss[2], fmaf(w1[(2 * p + 1) * 2 + 1], ss[3], b1[2 * p + 1]));
    fb1p[p] = make_float2(a0, a1);
  }
}

// ---------------- per-row layers ----------------
// 2 rows, shared weight loads
__device__ __forceinline__ void compute_h1_2(const float2* w1p, const float2* fb1p,
                                             float2 xa, float2 xb, float (&h)[2][16]) {
  u64 a0 = pack2(xa.x, xa.x), a1 = pack2(xa.y, xa.y);
  u64 b0 = pack2(xb.x, xb.x), b1 = pack2(xb.y, xb.y);
#pragma unroll
  for (int p = 0; p < 8; p++) {
    u64 fb = ldu64(&fb1p[p]);
    u64 w0 = ldu64(&w1p[p]);
    u64 w1v = ldu64(&w1p[8 + p]);
    u64 ra = fma2(w1v, a1, fma2(w0, a0, fb));
    u64 rb = fma2(w1v, b1, fma2(w0, b0, fb));
    float lo, hi;
    unpack2(ra, lo, hi);
    h[0][2 * p] = fmaxf(lo, 0.f); h[0][2 * p + 1] = fmaxf(hi, 0.f);
    unpack2(rb, lo, hi);
    h[1][2 * p] = fmaxf(lo, 0.f); h[1][2 * p + 1] = fmaxf(hi, 0.f);
  }
}

// 2 rows per thread, LDS.128 weights shared across rows
__device__ __forceinline__ void layer16_2(const float4* wq, const float2* fbp,
                                          const float (&v)[2][16], float (&o)[2][16]) {
  u64 acc[2][8];
#pragma unroll
  for (int p = 0; p < 8; p++) {
    u64 b = ldu64(&fbp[p]);
    acc[0][p] = b; acc[1][p] = b;
  }
#pragma unroll
  for (int j = 0; j < 16; j++) {
    u64 v0 = pack2(v[0][j], v[0][j]);
    u64 v1 = pack2(v[1][j], v[1][j]);
#pragma unroll
    for (int q = 0; q < 4; q++) {
      ulonglong2 w = ldu128(&wq[j * 4 + q]);
      acc[0][2 * q] = fma2(w.x, v0, acc[0][2 * q]);
      acc[0][2 * q + 1] = fma2(w.y, v0, acc[0][2 * q + 1]);
      acc[1][2 * q] = fma2(w.x, v1, acc[1][2 * q]);
      acc[1][2 * q + 1] = fma2(w.y, v1, acc[1][2 * q + 1]);
    }
  }
#pragma unroll
  for (int r = 0; r < 2; r++)
#pragma unroll
    for (int p = 0; p < 8; p++) {
      float a, b; unpack2(acc[r][p], a, b);
      o[r][2 * p] = fmaxf(a, 0.f);
      o[r][2 * p + 1] = fmaxf(b, 0.f);
    }
}

// single-row version (k_final phase A)
__device__ __forceinline__ void layer16_1(const float4* wq, const float2* fbp,
                                          const float (&v)[16], float (&o)[16]) {
  u64 acc[8];
#pragma unroll
  for (int p = 0; p < 8; p++) acc[p] = ldu64(&fbp[p]);
#pragma unroll
  for (int j = 0; j < 16; j++) {
    u64 vr = pack2(v[j], v[j]);
#pragma unroll
    for (int q = 0; q < 4; q++) {
      ulonglong2 w = ldu128(&wq[j * 4 + q]);
      acc[2 * q] = fma2(w.x, vr, acc[2 * q]);
      acc[2 * q + 1] = fma2(w.y, vr, acc[2 * q + 1]);
    }
  }
#pragma unroll
  for (int p = 0; p < 8; p++) {
    float a, b; unpack2(acc[p], a, b);
    o[2 * p] = fmaxf(a, 0.f);
    o[2 * p + 1] = fmaxf(b, 0.f);
  }
}

__device__ __forceinline__ void load_h2(int row, float (&h)[16]) {
#pragma unroll
  for (int p = 0; p < 4; p++) {
    float4 f = g_h2[p * CAP + row];
    h[4 * p] = f.x; h[4 * p + 1] = f.y; h[4 * p + 2] = f.z; h[4 * p + 3] = f.w;
  }
}

__device__ __forceinline__ void stats_add(const float (&h)[16], u64 (&sum2)[8], u64 (&sq2)[8]) {
#pragma unroll
  for (int p = 0; p < 8; p++) {
    u64 hp = pack2(h[2 * p], h[2 * p + 1]);
    sum2[p] = add2(sum2[p], hp);
    sq2[p] = fma2(hp, hp, sq2[p]);
  }
}

__device__ void stats_flush(int stage, float* sAcc, u64 (&sum2)[8], u64 (&sq2)[8]) {
#pragma unroll
  for (int p = 0; p < 8; p++) {
#pragma unroll
    for (int o = 16; o > 0; o >>= 1) {
      sum2[p] = add2(sum2[p], __shfl_xor_sync(0xffffffffu, sum2[p], o));
      sq2[p] = add2(sq2[p], __shfl_xor_sync(0xffffffffu, sq2[p], o));
    }
    if ((threadIdx.x & 31) == 0) {
      float a, b;
      unpack2(sum2[p], a, b);
      atomicAdd(&sAcc[2 * p], a); atomicAdd(&sAcc[2 * p + 1], b);
      unpack2(sq2[p], a, b);
      atomicAdd(&sAcc[16 + 2 * p], a); atomicAdd(&sAcc[16 + 2 * p + 1], b);
    }
  }
  __syncthreads();
  if (threadIdx.x < 32) atomicAdd(&g_stats[stage][threadIdx.x], sAcc[threadIdx.x]);
}

// ---------------- K0 ----------------
__global__ void k_setup(const float* __restrict__ emb, const float* __restrict__ wc,
                        const float* __restrict__ bc) {
  int t = threadIdx.x;  // 512
  if (t < 160) ((float*)g_stats)[t] = 0.f;
  int p = t >> 6, u = t & 63;
  float a = bc[u];
#pragma unroll
  for (int k = 0; k < 16; k++) a = fmaf(emb[p * 16 + k], wc[u * 32 + 16 + k], a);
  g_ctab[t] = a;
}

// ---------------- K1 ----------------
__global__ void __launch_bounds__(TB) k_stats0(const float2* __restrict__ x, int n) {
  __shared__ float sAcc[4];
  if (threadIdx.x < 4) sAcc[threadIdx.x] = 0.f;
  __syncthreads();
  float s0 = 0.f, s1 = 0.f, q0 = 0.f, q1 = 0.f;
  int stride = gridDim.x * blockDim.x;
  for (int i = blockIdx.x * blockDim.x + threadIdx.x; i < n; i += stride) {
    float2 v = x[i];
    s0 += v.x; s1 += v.y;
    q0 = fmaf(v.x, v.x, q0); q1 = fmaf(v.y, v.y, q1);
  }
#pragma unroll
  for (int o = 16; o > 0; o >>= 1) {
    s0 += __shfl_xor_sync(0xffffffffu, s0, o);
    s1 += __shfl_xor_sync(0xffffffffu, s1, o);
    q0 += __shfl_xor_sync(0xffffffffu, q0, o);
    q1 += __shfl_xor_sync(0xffffffffu, q1, o);
  }
  if ((threadIdx.x & 31) == 0) {
    atomicAdd(&sAcc[0], s0); atomicAdd(&sAcc[1], s1);
    atomicAdd(&sAcc[2], q0); atomicAdd(&sAcc[3], q1);
  }
  __syncthreads();
  if (threadIdx.x < 2) {
    atomicAdd(&g_stats[0][threadIdx.x], sAcc[threadIdx.x]);
    atomicAdd(&g_stats[0][16 + threadIdx.x], sAcc[2 + threadIdx.x]);
  }
}

// ---------------- K2: h1, stats1 ----------------
__global__ void __launch_bounds__(TB) k_pass2(
    const float2* __restrict__ x, int n,
    const float* __restrict__ bn0g, const float* __restrict__ bn0b,
    const float* __restrict__ w1, const float* __restrict__ b1) {
  __shared__ float ss0[4];
  __shared__ float2 w1p[16], fb1p[8];
  __shared__ float sAcc[32];
  if (threadIdx.x < 32) sAcc[threadIdx.x] = 0.f;
  float invN = 1.0f / (float)n;
  fold_bn_layer1(invN, bn0g, bn0b, w1, b1, ss0, w1p, fb1p);
  __syncthreads();

  u64 sum2[8], sq2[8];
#pragma unroll
  for (int p = 0; p < 8; p++) { sum2[p] = 0ull; sq2[p] = 0ull; }
  int stride = gridDim.x * blockDim.x;
  for (int i = blockIdx.x * blockDim.x + threadIdx.x; i < n; i += 2 * stride) {
    int i1 = i + stride;
    float2 xa = x[i];
    float2 xb = (i1 < n) ? x[i1] : make_float2(0.f, 0.f);
    float h[2][16];
    compute_h1_2(w1p, fb1p, xa, xb, h);
    stats_add(h[0], sum2, sq2);
    if (i1 < n) stats_add(h[1], sum2, sq2);
  }
  stats_flush(1, sAcc, sum2, sq2);
}

// ---------------- K3: y1a, stats2 ----------------
__global__ void __launch_bounds__(TB) k_pass3(
    const float2* __restrict__ x, int n,
    const float* __restrict__ bn0g, const float* __restrict__ bn0b,
    const float* __restrict__ bn1g, const float* __restrict__ bn1b,
    const float* __restrict__ w1, const float* __restrict__ b1,
    const float* __restrict__ w2, const float* __restrict__ b2) {
  __shared__ float ss0[4];  __shared__ float2 w1p[16], fb1p[8];
  __shared__ float ss1[32]; __shared__ float4 w2q[64]; __shared__ float2 fb2p[8];
  __shared__ float sAcc[32];
  if (threadIdx.x < 32) sAcc[threadIdx.x] = 0.f;
  float invN = 1.0f / (float)n;
  fold_bn_layer1(invN, bn0g, bn0b, w1, b1, ss0, w1p, fb1p);
  fold_bn_layer16(1, invN, bn1g, bn1b, w2, b2, ss1, w2q, fb2p);
  __syncthreads();

  u64 sum2[8], sq2[8];
#pragma unroll
  for (int p = 0; p < 8; p++) { sum2[p] = 0ull; sq2[p] = 0ull; }
  int stride = gridDim.x * blockDim.x;
  for (int i = blockIdx.x * blockDim.x + threadIdx.x; i < n; i += 2 * stride) {
    int i1 = i + stride;
    float2 xa = x[i];
    float2 xb = (i1 < n) ? x[i1] : make_float2(0.f, 0.f);
    float h[2][16], y[2][16];
    compute_h1_2(w1p, fb1p, xa, xb, h);
    layer16_2(w2q, fb2p, h, y);
    stats_add(y[0], sum2, sq2);
    if (i1 < n) stats_add(y[1], sum2, sq2);
  }
  stats_flush(2, sAcc, sum2, sq2);
}

// ---------------- K4: h2 = h1 + L3(BN2 y1a); store; stats3 ----------------
__global__ void __launch_bounds__(TB) k_pass4(
    const float2* __restrict__ x, int n,
    const float* __restrict__ bn0g, const float* __restrict__ bn0b,
    const float* __restrict__ bn1g, const float* __restrict__ bn1b,
    const float* __restrict__ bn2g, const float* __restrict__ bn2b,
    const float* __restrict__ w1, const float* __restrict__ b1,
    const float* __restrict__ w2, const float* __restrict__ b2,
    const float* __restrict__ w3, const float* __restrict__ b3) {
  __shared__ float ss0[4];  __shared__ float2 w1p[16], fb1p[8];
  __shared__ float ss1[32]; __shared__ float4 w2q[64]; __shared__ float2 fb2p[8];
  __shared__ float ss2[32]; __shared__ float4 w3q[64]; __shared__ float2 fb3p[8];
  __shared__ float sAcc[32];
  if (threadIdx.x < 32) sAcc[threadIdx.x] = 0.f;
  float invN = 1.0f / (float)n;
  fold_bn_layer1(invN, bn0g, bn0b, w1, b1, ss0, w1p, fb1p);
  fold_bn_layer16(1, invN, bn1g, bn1b, w2, b2, ss1, w2q, fb2p);
  fold_bn_layer16(2, invN, bn2g, bn2b, w3, b3, ss2, w3q, fb3p);
  __syncthreads();

  u64 sum2[8], sq2[8];
#pragma unroll
  for (int p = 0; p < 8; p++) { sum2[p] = 0ull; sq2[p] = 0ull; }
  int stride = gridDim.x * blockDim.x;
  for (int i = blockIdx.x * blockDim.x + threadIdx.x; i < n; i += 2 * stride) {
    int i1 = i + stride;
    float2 xa = x[i];
    float2 xb = (i1 < n) ? x[i1] : make_float2(0.f, 0.f);
    float h[2][16], y[2][16], z[2][16];
    compute_h1_2(w1p, fb1p, xa, xb, h);
    layer16_2(w2q, fb2p, h, y);
    layer16_2(w3q, fb3p, y, z);
#pragma unroll
    for (int r = 0; r < 2; r++)
#pragma unroll
      for (int c = 0; c < 16; c++) h[r][c] += z[r][c];   // h2
#pragma unroll
    for (int p = 0; p < 4; p++)
      g_h2[p * CAP + i] = make_float4(h[0][4 * p], h[0][4 * p + 1], h[0][4 * p + 2], h[0][4 * p + 3]);
    stats_add(h[0], sum2, sq2);
    if (i1 < n) {
#pragma unroll
      for (int p = 0; p < 4; p++)
        g_h2[p * CAP + i1] = make_float4(h[1][4 * p], h[1][4 * p + 1], h[1][4 * p + 2], h[1][4 * p + 3]);
      stats_add(h[1], sum2, sq2);
    }
  }
  stats_flush(3, sAcc, sum2, sq2);
}

// ---------------- K5: y2a, stats4 ----------------
__global__ void __launch_bounds__(TB) k_pass5(
    int n,
    const float* __restrict__ bn3g, const float* __restrict__ bn3b,
    const float* __restrict__ w4, const float* __restrict__ b4) {
  __shared__ float ss3[32]; __shared__ float4 w4q[64]; __shared__ float2 fb4p[8];
  __shared__ float sAcc[32];
  if (threadIdx.x < 32) sAcc[threadIdx.x] = 0.f;
  float invN = 1.0f / (float)n;
  fold_bn_layer16(3, invN, bn3g, bn3b, w4, b4, ss3, w4q, fb4p);
  __syncthreads();

  u64 sum2[8], sq2[8];
#pragma unroll
  for (int p = 0; p < 8; p++) { sum2[p] = 0ull; sq2[p] = 0ull; }
  int stride = gridDim.x * blockDim.x;
  for (int i = blockIdx.x * blockDim.x + threadIdx.x; i < n; i += 2 * stride) {
    int i1 = i + stride;
    float h[2][16], y[2][16];
    load_h2(i, h[0]);
    if (i1 < n) load_h2(i1, h[1]);
    else {
#pragma unroll
      for (int c = 0; c < 16; c++) h[1][c] = 0.f;
    }
    layer16_2(w4q, fb4p, h, y);
    stats_add(y[0], sum2, sq2);
    if (i1 < n) stats_add(y[1], sum2, sq2);
  }
  stats_flush(4, sAcc, sum2, sq2);
}

// ---------------- K6: final — phase A per-thread rows, phase B warp-coop classifier ----------------
__global__ void __launch_bounds__(TB) k_final(
    int n, const int* __restrict__ idx, float* __restrict__ out,
    const float* __restrict__ bn3g, const float* __restrict__ bn3b,
    const float* __restrict__ bn4g, const float* __restrict__ bn4b,
    const float* __restrict__ w4, const float* __restrict__ b4,
    const float* __restrict__ w5, const float* __restrict__ b5,
    const float* __restrict__ wc) {
  __shared__ float ss3[32]; __shared__ float4 w4q[64]; __shared__ float2 fb4p[8];
  __shared__ float ss4[32]; __shared__ float4 w5q[64]; __shared__ float2 fb5p[8];
  __shared__ float2 swcp[512];        // swcp[kp*64+c] = (wc[c][2kp], wc[c][2kp+1]) head
  __shared__ float2 sct2[256];        // ctab as u64 pairs [part*32 + cpair]
  __shared__ float2 sh3[TB * 9];      // staged h3, row stride 9 u64 (conflict-padded)
  __shared__ int spart[TB];
  float invN = 1.0f / (float)n;
  fold_bn_layer16(3, invN, bn3g, bn3b, w4, b4, ss3, w4q, fb4p);
  fold_bn_layer16(4, invN, bn4g, bn4b, w5, b5, ss4, w5q, fb5p);
  int t = threadIdx.x;
  int lane = t & 31, wid = t >> 5;
  {
#pragma unroll
    for (int e = t; e < 512; e += TB) {
      int kp = e >> 6, c = e & 63;
      swcp[e] = make_float2(wc[c * 32 + 2 * kp], wc[c * 32 + 2 * kp + 1]);
    }
    sct2[t] = ((const float2*)g_ctab)[t];
  }
  __syncthreads();

  int blockBase = blockIdx.x * TB;
  int i = blockBase + t;

  // phase A: per-thread row -> h3 staged to smem
  {
    float h[16], y[16], z[16];
    int part = 0;
    if (i < n) {
      load_h2(i, h);
      layer16_1(w4q, fb4p, h, y);
      layer16_1(w5q, fb5p, y, z);
      part = idx[i];
    } else {
#pragma unroll
      for (int c = 0; c < 16; c++) { h[c] = 0.f; z[c] = 0.f; }
    }
#pragma unroll
    for (int kp = 0; kp < 8; kp++)
      *reinterpret_cast<u64*>(&sh3[t * 9 + kp]) = pack2(h[2 * kp] + z[2 * kp], h[2 * kp + 1] + z[2 * kp + 1]);
    spart[t] = part;
  }
  __syncthreads();

  // phase B: per-lane classifier weights in registers (cols 2*lane, 2*lane+1)
  u64 wl[8], wh[8];
#pragma unroll
  for (int kp = 0; kp < 8; kp++) {
    wl[kp] = ldu64(&swcp[kp * 64 + 2 * lane]);
    wh[kp] = ldu64(&swcp[kp * 64 + 2 * lane + 1]);
  }

  // warp `wid` handles rows [wid*32, wid*32+32) of this block
  int rowsLeft = n - blockBase - wid * 32;
  int rCount = rowsLeft < 32 ? (rowsLeft < 0 ? 0 : rowsLeft) : 32;
  for (int r = 0; r < rCount; r++) {
    int lrow = wid * 32 + r;
    int part = spart[lrow];                  // broadcast
    u64 hp[8];
#pragma unroll
    for (int kp = 0; kp < 8; kp++) hp[kp] = *reinterpret_cast<const u64*>(&sh3[lrow * 9 + kp]);  // broadcast
    u64 accL = 0ull, accH = 0ull;
#pragma unroll
    for (int kp = 0; kp < 8; kp++) {
      accL = fma2(wl[kp], hp[kp], accL);
      accH = fma2(wh[kp], hp[kp], accH);
    }
    float la, lb, ha, hb, ca, cb;
    unpack2(accL, la, lb);
    unpack2(accH, ha, hb);
    unpack2(ldu64(&sct2[part * 32 + lane]), ca, cb);
    u64 res = pack2(la + lb + ca, ha + hb + cb);
    // row write: 32 lanes x 8B contiguous = 256B coalesced
    *reinterpret_cast<u64*>(out + (size_t)(blockBase + lrow) * 64 + 2 * lane) = res;
  }
}

// ---------------- launch ----------------
extern "C" void kernel_launch(void* const* d_in, const int* in_sizes, int n_in,
                              void* d_out, int out_size) {
  const float2* x  = (const float2*)d_in[0];
  const int* idx   = (const int*)d_in[1];
  const float* bn0g = (const float*)d_in[2],  *bn0b = (const float*)d_in[3];
  const float* bn1g = (const float*)d_in[4],  *bn1b = (const float*)d_in[5];
  const float* bn2g = (const float*)d_in[6],  *bn2b = (const float*)d_in[7];
  const float* bn3g = (const float*)d_in[8],  *bn3b = (const float*)d_in[9];
  const float* bn4g = (const float*)d_in[10], *bn4b = (const float*)d_in[11];
  const float* w1 = (const float*)d_in[12], *b1 = (const float*)d_in[13];
  const float* w2 = (const float*)d_in[14], *b2 = (const float*)d_in[15];
  const float* w3 = (const float*)d_in[16], *b3 = (const float*)d_in[17];
  const float* w4 = (const float*)d_in[18], *b4 = (const float*)d_in[19];
  const float* w5 = (const float*)d_in[20], *b5 = (const float*)d_in[21];
  const float* emb = (const float*)d_in[22];
  const float* wc  = (const float*)d_in[23], *bc = (const float*)d_in[24];
  float* out = (float*)d_out;
  int n = in_sizes[1];

  k_setup<<<1, 512>>>(emb, wc, bc);
  k_stats0<<<SGRID, TB>>>(x, n);
  k_pass2<<<SGRID, TB>>>(x, n, bn0g, bn0b, w1, b1);
  k_pass3<<<SGRID, TB>>>(x, n, bn0g, bn0b, bn1g, bn1b, w1, b1, w2, b2);
  k_pass4<<<SGRID, TB>>>(x, n, bn0g, bn0b, bn1g, bn1b, bn2g, bn2b, w1, b1, w2, b2, w3, b3);
  k_pass5<<<SGRID, TB>>>(n, bn3g, bn3b, w4, b4);
  k_final<<<(n + TB - 1) / TB, TB>>>(n, idx, out, bn3g, bn3b, bn4g, bn4b, w4, b4, w5, b5, wc);
}